// round 15
// baseline (speedup 1.0000x reference)
#include <cuda_runtime.h>
#include <cuda_bf16.h>
#include <math.h>
#include <stdint.h>

// Problem constants
#define NB 4          // batch
#define CC 512        // channels C
#define KPD 512       // key planes
#define NP 4096       // H*W
#define MP 4096       // HS*WS

// ============================================================================
// bf16 split helpers
// ============================================================================
__device__ __forceinline__ uint32_t bpack2(float v0, float v1,
                                           uint32_t& lo_out) {
    __nv_bfloat16 h0 = __float2bfloat16(v0);
    __nv_bfloat16 h1 = __float2bfloat16(v1);
    __nv_bfloat16 l0 = __float2bfloat16(v0 - __bfloat162float(h0));
    __nv_bfloat16 l1 = __float2bfloat16(v1 - __bfloat162float(h1));
    uint16_t uh0 = *reinterpret_cast<uint16_t*>(&h0);
    uint16_t uh1 = *reinterpret_cast<uint16_t*>(&h1);
    uint16_t ul0 = *reinterpret_cast<uint16_t*>(&l0);
    uint16_t ul1 = *reinterpret_cast<uint16_t*>(&l1);
    lo_out = (uint32_t)ul0 | ((uint32_t)ul1 << 16);
    return (uint32_t)uh0 | ((uint32_t)uh1 << 16);
}

// ============================================================================
// HMMA / ldmatrix / cp.async (portable sm_80+ PTX — valid on plain sm_103)
// ============================================================================
__device__ __forceinline__ uint32_t smem_u32(const void* p) {
    uint32_t a;
    asm("{ .reg .u64 t; cvta.to.shared.u64 t, %1; cvt.u32.u64 %0, t; }"
        : "=r"(a) : "l"(p));
    return a;
}

#define LDM_X4(r0, r1, r2, r3, a) \
    asm volatile("ldmatrix.sync.aligned.m8n8.x4.shared.b16 {%0,%1,%2,%3}, [%4];" \
                 : "=r"(r0), "=r"(r1), "=r"(r2), "=r"(r3) : "r"(a))

__device__ __forceinline__ void mma16816(float* d, const uint32_t* a,
                                         uint32_t b0, uint32_t b1) {
    asm volatile(
        "mma.sync.aligned.m16n8k16.row.col.f32.bf16.bf16.f32 "
        "{%0,%1,%2,%3}, {%4,%5,%6,%7}, {%8,%9}, {%0,%1,%2,%3};"
        : "+f"(d[0]), "+f"(d[1]), "+f"(d[2]), "+f"(d[3])
        : "r"(a[0]), "r"(a[1]), "r"(a[2]), "r"(a[3]), "r"(b0), "r"(b1));
}

#define CP_ASYNC16(dst, src) \
    asm volatile("cp.async.cg.shared.global [%0], [%1], 16;" \
                 :: "r"(dst), "l"(src))
#define CP_COMMIT() asm volatile("cp.async.commit_group;" ::: "memory")
#define CP_WAIT0()  asm volatile("cp.async.wait_group 0;" ::: "memory")
#define CP_WAIT1()  asm volatile("cp.async.wait_group 1;" ::: "memory")

// ============================================================================
// Device-global scratch (alloc-free per harness rules)
// ============================================================================
__device__ float g_S[(size_t)NB * NP * MP];              // logits f32
__device__ __nv_bfloat16 g_Fh[(size_t)NB * NP * KPD];    // F [b][n][k] hi
__device__ __nv_bfloat16 g_Fl[(size_t)NB * NP * KPD];
__device__ __nv_bfloat16 g_Gh[(size_t)NB * MP * KPD];    // G [b][m][k]
__device__ __nv_bfloat16 g_Gl[(size_t)NB * MP * KPD];
__device__ __nv_bfloat16 g_Hth[(size_t)NB * CC * MP];    // Ht [b][c][m]
__device__ __nv_bfloat16 g_Htl[(size_t)NB * CC * MP];
__device__ __nv_bfloat16 g_Qh [(size_t)NB * CC * MP];    // Ht^2 [b][c][m]
__device__ __nv_bfloat16 g_Ql [(size_t)NB * CC * MP];
__device__ __nv_bfloat16 g_Sh[(size_t)NB * NP * MP];     // softmax probs
__device__ __nv_bfloat16 g_Sl[(size_t)NB * NP * MP];
// Conv staging (reused sequentially for c_1x, s_1x, s_x)
__device__ __nv_bfloat16 g_Xth[(size_t)NB * NP * KPD];   // X^T [b][i][k] hi
__device__ __nv_bfloat16 g_Xtl[(size_t)NB * NP * KPD];
__device__ __nv_bfloat16 g_Wh[(size_t)KPD * KPD];        // W [j][k] hi
__device__ __nv_bfloat16 g_Wl[(size_t)KPD * KPD];

// ============================================================================
// Split / transpose kernels
// ============================================================================
__global__ void __launch_bounds__(256)
split_xt(const float* __restrict__ X)
{
    __shared__ float tile[32][33];
    int b = blockIdx.z;
    int i0 = blockIdx.x * 32, k0 = blockIdx.y * 32;
    int tx = threadIdx.x & 31, ty = threadIdx.x >> 5;   // ty 0..7
    const float* Xb = X + (size_t)b * KPD * NP;
#pragma unroll
    for (int r = 0; r < 4; r++) {
        int k = ty + r * 8;
        tile[k][tx] = Xb[(size_t)(k0 + k) * NP + i0 + tx];
    }
    __syncthreads();
    size_t ob = (size_t)b * NP * KPD;
#pragma unroll
    for (int r = 0; r < 4; r++) {
        int i = ty + r * 8;
        float v = tile[tx][i];
        __nv_bfloat16 h = __float2bfloat16(v);
        __nv_bfloat16 l = __float2bfloat16(v - __bfloat162float(h));
        size_t idx = ob + (size_t)(i0 + i) * KPD + k0 + tx;
        g_Xth[idx] = h;
        g_Xtl[idx] = l;
    }
}

__global__ void __launch_bounds__(256)
split_wk(const float* __restrict__ W)
{
    int idx = blockIdx.x * 256 + threadIdx.x;   // each handles 2 floats
    float2 v = reinterpret_cast<const float2*>(W)[idx];
    uint32_t lo;
    uint32_t hi = bpack2(v.x, v.y, lo);
    reinterpret_cast<uint32_t*>(g_Wh)[idx] = hi;
    reinterpret_cast<uint32_t*>(g_Wl)[idx] = lo;
}

// ============================================================================
// Pipeline geometry (KC = 16): each array = 128 rows x 48B stride (32B data).
// 48B stride is 16B-aligned for cp.async and conflict-free for ldmatrix
// (chunk addrs mod 128: 0,48,96,16,64,112,32,80 — all distinct).
// ============================================================================
#define P_ARR  6144
#define P_STG  (4 * P_ARR)
#define P_SMEM (2 * P_STG)      // 49152 -> 4 CTAs/SM

#define M_ARR  6144
#define M_STG  (6 * M_ARR)
#define M_SMEM (2 * M_STG)      // 73728 -> 3 CTAs/SM

// ============================================================================
// Core 128x128 3-term mainloop for one KC=16 stage.
// A rows: warp wn (0..3) covers 32; B cols: warp wm (0..1) covers 64.
// MMA issue order interleaves p0/p1 chains for ILP.
// ============================================================================
__device__ __forceinline__ void hmma_mainloop_stage(uint32_t base, int lane,
                                                    int wn, int wm,
                                                    float d[2][8][4])
{
    int r8 = lane & 7;
    uint32_t Ah[2][4], Al[2][4];
    int arow = r8 + ((lane >> 3) & 1) * 8;
    int akb  = ((lane >> 4) & 1) * 8;
#pragma unroll
    for (int nt = 0; nt < 2; nt++) {
        uint32_t aoff = (uint32_t)((wn * 32 + nt * 16 + arow) * 48 + akb * 2);
        LDM_X4(Ah[nt][0], Ah[nt][1], Ah[nt][2], Ah[nt][3], base + 0 * P_ARR + aoff);
        LDM_X4(Al[nt][0], Al[nt][1], Al[nt][2], Al[nt][3], base + 1 * P_ARR + aoff);
    }
    int brow = r8 + ((lane >> 4) & 1) * 8;
    int bkb  = ((lane >> 3) & 1) * 8;
#pragma unroll
    for (int mg = 0; mg < 4; mg++) {
        uint32_t boff = (uint32_t)((wm * 64 + mg * 16 + brow) * 48 + bkb * 2);
        uint32_t Bh[4], Bl[4];
        LDM_X4(Bh[0], Bh[1], Bh[2], Bh[3], base + 2 * P_ARR + boff);
        LDM_X4(Bl[0], Bl[1], Bl[2], Bl[3], base + 3 * P_ARR + boff);
#pragma unroll
        for (int nt = 0; nt < 2; nt++) {
            float* p0 = d[nt][2 * mg];
            float* p1 = d[nt][2 * mg + 1];
            mma16816(p0, Ah[nt], Bh[0], Bh[1]);
            mma16816(p1, Ah[nt], Bh[2], Bh[3]);
            mma16816(p0, Ah[nt], Bl[0], Bl[1]);
            mma16816(p1, Ah[nt], Bl[2], Bl[3]);
            mma16816(p0, Al[nt], Bh[0], Bh[1]);
            mma16816(p1, Al[nt], Bh[2], Bh[3]);
        }
    }
}

// ============================================================================
// Conv GEMM via HMMA. stages = KPD/16 = 32.
// ============================================================================
#define C_STAGES (KPD / 16)

__device__ __forceinline__ void conv_issue(int s, uint32_t sb, int tid,
                                           size_t xb, int a0, int b0, int swap)
{
    uint32_t base = sb + (uint32_t)(s & 1) * P_STG;
    int k0 = s * 16;
#pragma unroll
    for (int q = 0; q < 4; q++) {
        int id = q * 256 + tid;
        int arr = id >> 8, rem = id & 255, row = rem >> 1, c = rem & 1;
        const __nv_bfloat16* src;
        if (!swap) {
            if (arr == 0)      src = g_Xth + xb + (size_t)(a0 + row) * KPD + k0 + c * 8;
            else if (arr == 1) src = g_Xtl + xb + (size_t)(a0 + row) * KPD + k0 + c * 8;
            else if (arr == 2) src = g_Wh + (size_t)(b0 + row) * KPD + k0 + c * 8;
            else               src = g_Wl + (size_t)(b0 + row) * KPD + k0 + c * 8;
        } else {
            if (arr == 0)      src = g_Wh + (size_t)(a0 + row) * KPD + k0 + c * 8;
            else if (arr == 1) src = g_Wl + (size_t)(a0 + row) * KPD + k0 + c * 8;
            else if (arr == 2) src = g_Xth + xb + (size_t)(b0 + row) * KPD + k0 + c * 8;
            else               src = g_Xtl + xb + (size_t)(b0 + row) * KPD + k0 + c * 8;
        }
        uint32_t dst = base + (uint32_t)arr * P_ARR + row * 48 + c * 16;
        CP_ASYNC16(dst, (const void*)src);
    }
    CP_COMMIT();
}

// dest 0 -> F, 1 -> G: output [n][k] split, bias over columns
__global__ void __launch_bounds__(256)
conv_nk(const float* __restrict__ bias, int dest)
{
    extern __shared__ char sm[];
    uint32_t sb = smem_u32(sm);
    int tid = threadIdx.x, lane = tid & 31, warp = tid >> 5;
    int wn = warp >> 1, wm = warp & 1;
    int b = blockIdx.z, i0 = blockIdx.x * 128, j0 = blockIdx.y * 128;
    size_t xb = (size_t)b * NP * KPD;

    float d[2][8][4];
#pragma unroll
    for (int a = 0; a < 2; a++)
#pragma unroll
        for (int j = 0; j < 8; j++)
#pragma unroll
            for (int r = 0; r < 4; r++) d[a][j][r] = 0.f;

    conv_issue(0, sb, tid, xb, i0, j0, 0);
    for (int s = 0; s < C_STAGES; s++) {
        if (s + 1 < C_STAGES) { conv_issue(s + 1, sb, tid, xb, i0, j0, 0); CP_WAIT1(); }
        else                  { CP_WAIT0(); }
        __syncthreads();
        hmma_mainloop_stage(sb + (uint32_t)(s & 1) * P_STG, lane, wn, wm, d);
        __syncthreads();
    }

    size_t bb = (size_t)b * NP * KPD;
    __nv_bfloat16* Dh = (dest == 0 ? g_Fh : g_Gh) + bb;
    __nv_bfloat16* Dl = (dest == 0 ? g_Fl : g_Gl) + bb;
#pragma unroll
    for (int nt = 0; nt < 2; nt++)
#pragma unroll
        for (int m8 = 0; m8 < 8; m8++) {
            int n = i0 + wn * 32 + nt * 16 + (lane >> 2);
            int j = j0 + wm * 64 + m8 * 8 + (lane & 3) * 2;
            float2 bv = *reinterpret_cast<const float2*>(&bias[j]);
            uint32_t lo, hi;
            hi = bpack2(d[nt][m8][0] + bv.x, d[nt][m8][1] + bv.y, lo);
            *reinterpret_cast<uint32_t*>(Dh + (size_t)n * KPD + j) = hi;
            *reinterpret_cast<uint32_t*>(Dl + (size_t)n * KPD + j) = lo;
            hi = bpack2(d[nt][m8][2] + bv.x, d[nt][m8][3] + bv.y, lo);
            *reinterpret_cast<uint32_t*>(Dh + (size_t)(n + 8) * KPD + j) = hi;
            *reinterpret_cast<uint32_t*>(Dl + (size_t)(n + 8) * KPD + j) = lo;
        }
}

// Ht conv: output rows = channels -> Ht [c][m] and Ht^2 [c][m] splits
__global__ void __launch_bounds__(256)
conv_cm(const float* __restrict__ bias)
{
    extern __shared__ char sm[];
    uint32_t sb = smem_u32(sm);
    int tid = threadIdx.x, lane = tid & 31, warp = tid >> 5;
    int wc = warp >> 1, wm = warp & 1;
    int b = blockIdx.z, m0 = blockIdx.x * 128, c0 = blockIdx.y * 128;
    size_t xb = (size_t)b * NP * KPD;

    float d[2][8][4];
#pragma unroll
    for (int a = 0; a < 2; a++)
#pragma unroll
        for (int j = 0; j < 8; j++)
#pragma unroll
            for (int r = 0; r < 4; r++) d[a][j][r] = 0.f;

    conv_issue(0, sb, tid, xb, c0, m0, 1);
    for (int s = 0; s < C_STAGES; s++) {
        if (s + 1 < C_STAGES) { conv_issue(s + 1, sb, tid, xb, c0, m0, 1); CP_WAIT1(); }
        else                  { CP_WAIT0(); }
        __syncthreads();
        hmma_mainloop_stage(sb + (uint32_t)(s & 1) * P_STG, lane, wc, wm, d);
        __syncthreads();
    }

    size_t bb = (size_t)b * CC * MP;
#pragma unroll
    for (int ct = 0; ct < 2; ct++)
#pragma unroll
        for (int m8 = 0; m8 < 8; m8++) {
            int c = c0 + wc * 32 + ct * 16 + (lane >> 2);
            int m = m0 + wm * 64 + m8 * 8 + (lane & 3) * 2;
            float b0v = bias[c], b1v = bias[c + 8];
            float v0 = d[ct][m8][0] + b0v, v1 = d[ct][m8][1] + b0v;
            float v2 = d[ct][m8][2] + b1v, v3 = d[ct][m8][3] + b1v;
            size_t idx0 = bb + (size_t)c * MP + m;
            size_t idx1 = bb + (size_t)(c + 8) * MP + m;
            uint32_t lo, hi;
            hi = bpack2(v0, v1, lo);
            *reinterpret_cast<uint32_t*>(g_Hth + idx0) = hi;
            *reinterpret_cast<uint32_t*>(g_Htl + idx0) = lo;
            hi = bpack2(v0 * v0, v1 * v1, lo);
            *reinterpret_cast<uint32_t*>(g_Qh + idx0) = hi;
            *reinterpret_cast<uint32_t*>(g_Ql + idx0) = lo;
            hi = bpack2(v2, v3, lo);
            *reinterpret_cast<uint32_t*>(g_Hth + idx1) = hi;
            *reinterpret_cast<uint32_t*>(g_Htl + idx1) = lo;
            hi = bpack2(v2 * v2, v3 * v3, lo);
            *reinterpret_cast<uint32_t*>(g_Qh + idx1) = hi;
            *reinterpret_cast<uint32_t*>(g_Ql + idx1) = lo;
        }
}

// ============================================================================
// Logits GEMM via HMMA. stages = KPD/16 = 32.
// ============================================================================
#define L_STAGES (KPD / 16)

__device__ __forceinline__ void logits_issue(int s, uint32_t sb, int tid,
                                             int b, int n0, int m0)
{
    uint32_t base = sb + (uint32_t)(s & 1) * P_STG;
    int k0 = s * 16;
    size_t fb = (size_t)b * NP * KPD;
    size_t gb = (size_t)b * MP * KPD;
#pragma unroll
    for (int q = 0; q < 4; q++) {
        int id = q * 256 + tid;
        int arr = id >> 8, rem = id & 255, row = rem >> 1, c = rem & 1;
        const __nv_bfloat16* src;
        if (arr == 0)      src = g_Fh + fb + (size_t)(n0 + row) * KPD + k0 + c * 8;
        else if (arr == 1) src = g_Fl + fb + (size_t)(n0 + row) * KPD + k0 + c * 8;
        else if (arr == 2) src = g_Gh + gb + (size_t)(m0 + row) * KPD + k0 + c * 8;
        else               src = g_Gl + gb + (size_t)(m0 + row) * KPD + k0 + c * 8;
        uint32_t dst = base + (uint32_t)arr * P_ARR + row * 48 + c * 16;
        CP_ASYNC16(dst, (const void*)src);
    }
    CP_COMMIT();
}

__global__ void __launch_bounds__(256)
logits_hmma()
{
    extern __shared__ char sm[];
    uint32_t sb = smem_u32(sm);
    int tid = threadIdx.x, lane = tid & 31, warp = tid >> 5;
    int wn = warp >> 1, wm = warp & 1;
    int b = blockIdx.z, m0 = blockIdx.x * 128, n0 = blockIdx.y * 128;
    float* Sb = g_S + (size_t)b * NP * MP;

    float d[2][8][4];
#pragma unroll
    for (int a = 0; a < 2; a++)
#pragma unroll
        for (int j = 0; j < 8; j++)
#pragma unroll
            for (int r = 0; r < 4; r++) d[a][j][r] = 0.f;

    logits_issue(0, sb, tid, b, n0, m0);
    for (int s = 0; s < L_STAGES; s++) {
        if (s + 1 < L_STAGES) { logits_issue(s + 1, sb, tid, b, n0, m0); CP_WAIT1(); }
        else                  { CP_WAIT0(); }
        __syncthreads();
        hmma_mainloop_stage(sb + (uint32_t)(s & 1) * P_STG, lane, wn, wm, d);
        __syncthreads();
    }

#pragma unroll
    for (int nt = 0; nt < 2; nt++)
#pragma unroll
        for (int m8 = 0; m8 < 8; m8++) {
            int n = n0 + wn * 32 + nt * 16 + (lane >> 2);
            int m = m0 + wm * 64 + m8 * 8 + (lane & 3) * 2;
            *reinterpret_cast<float2*>(&Sb[(size_t)n * MP + m]) =
                make_float2(d[nt][m8][0], d[nt][m8][1]);
            *reinterpret_cast<float2*>(&Sb[(size_t)(n + 8) * MP + m]) =
                make_float2(d[nt][m8][2], d[nt][m8][3]);
        }
}

// ============================================================================
// Row softmax: f32 logits -> bf16 hi/lo probabilities.
// ============================================================================
__global__ void __launch_bounds__(256)
softmax_rows()
{
    __shared__ float red[256];
    int row = blockIdx.x;
    size_t base = (size_t)row * MP;
    int tid = threadIdx.x;

    float2 v[8];
    float lmax = -1e30f;
#pragma unroll
    for (int t = 0; t < 8; t++) {
        v[t] = *reinterpret_cast<const float2*>(&g_S[base + tid * 2 + t * 512]);
        lmax = fmaxf(lmax, fmaxf(v[t].x, v[t].y));
    }
    red[tid] = lmax;
    __syncthreads();
    for (int s = 128; s > 0; s >>= 1) {
        if (tid < s) red[tid] = fmaxf(red[tid], red[tid + s]);
        __syncthreads();
    }
    float m = red[0];
    __syncthreads();

    float lsum = 0.f;
#pragma unroll
    for (int t = 0; t < 8; t++) {
        v[t].x = __expf(v[t].x - m);
        v[t].y = __expf(v[t].y - m);
        lsum += v[t].x + v[t].y;
    }
    red[tid] = lsum;
    __syncthreads();
    for (int s = 128; s > 0; s >>= 1) {
        if (tid < s) red[tid] += red[tid + s];
        __syncthreads();
    }
    float inv = 1.f / red[0];

#pragma unroll
    for (int t = 0; t < 8; t++) {
        size_t idx = base + tid * 2 + t * 512;
        uint32_t lo;
        uint32_t hi = bpack2(v[t].x * inv, v[t].y * inv, lo);
        *reinterpret_cast<uint32_t*>(&g_Sh[idx]) = hi;
        *reinterpret_cast<uint32_t*>(&g_Sl[idx]) = lo;
    }
}

// ============================================================================
// Dual GEMM (mean & e2) + fused epilogue. stages = MP/16 = 256.
// ============================================================================
#define M_STAGES (MP / 16)

__device__ __forceinline__ void meanstd_issue(int s, uint32_t sb, int tid,
                                              int b, int cc0, int n0)
{
    uint32_t base = sb + (uint32_t)(s & 1) * M_STG;
    int mm = s * 16;
    size_t hb = (size_t)b * CC * MP;
    size_t pb = (size_t)b * NP * MP;
#pragma unroll
    for (int q = 0; q < 6; q++) {
        int id = q * 256 + tid;
        int arr = id >> 8, rem = id & 255, row = rem >> 1, c = rem & 1;
        const __nv_bfloat16* src;
        if (arr == 0)      src = g_Hth + hb + (size_t)(cc0 + row) * MP + mm + c * 8;
        else if (arr == 1) src = g_Htl + hb + (size_t)(cc0 + row) * MP + mm + c * 8;
        else if (arr == 2) src = g_Qh  + hb + (size_t)(cc0 + row) * MP + mm + c * 8;
        else if (arr == 3) src = g_Ql  + hb + (size_t)(cc0 + row) * MP + mm + c * 8;
        else if (arr == 4) src = g_Sh  + pb + (size_t)(n0 + row) * MP + mm + c * 8;
        else               src = g_Sl  + pb + (size_t)(n0 + row) * MP + mm + c * 8;
        uint32_t dst = base + (uint32_t)arr * M_ARR + row * 48 + c * 16;
        CP_ASYNC16(dst, (const void*)src);
    }
    CP_COMMIT();
}

__global__ void __launch_bounds__(256)
meanstd_hmma(const float* __restrict__ c_x, float* __restrict__ out)
{
    extern __shared__ char sm[];
    uint32_t sb = smem_u32(sm);
    int tid = threadIdx.x, lane = tid & 31, warp = tid >> 5;
    int wc = warp >> 1, wn = warp & 1;
    int b = blockIdx.z, n0 = blockIdx.x * 128, cc0 = blockIdx.y * 128;

    float dm[2][8][4], de[2][8][4];
#pragma unroll
    for (int a = 0; a < 2; a++)
#pragma unroll
        for (int j = 0; j < 8; j++)
#pragma unroll
            for (int r = 0; r < 4; r++) { dm[a][j][r] = 0.f; de[a][j][r] = 0.f; }

    meanstd_issue(0, sb, tid, b, cc0, n0);

    int r8 = lane & 7;
    for (int s = 0; s < M_STAGES; s++) {
        if (s + 1 < M_STAGES) { meanstd_issue(s + 1, sb, tid, b, cc0, n0); CP_WAIT1(); }
        else                  { CP_WAIT0(); }
        __syncthreads();

        uint32_t base = sb + (uint32_t)(s & 1) * M_STG;
        uint32_t Hh[2][4], Hl[2][4], Wh[2][4], Wl[2][4];
        int arow = r8 + ((lane >> 3) & 1) * 8;
        int akb  = ((lane >> 4) & 1) * 8;
#pragma unroll
        for (int ct = 0; ct < 2; ct++) {
            uint32_t aoff = (uint32_t)((wc * 32 + ct * 16 + arow) * 48 + akb * 2);
            LDM_X4(Hh[ct][0], Hh[ct][1], Hh[ct][2], Hh[ct][3], base + 0 * M_ARR + aoff);
            LDM_X4(Hl[ct][0], Hl[ct][1], Hl[ct][2], Hl[ct][3], base + 1 * M_ARR + aoff);
            LDM_X4(Wh[ct][0], Wh[ct][1], Wh[ct][2], Wh[ct][3], base + 2 * M_ARR + aoff);
            LDM_X4(Wl[ct][0], Wl[ct][1], Wl[ct][2], Wl[ct][3], base + 3 * M_ARR + aoff);
        }
        int brow = r8 + ((lane >> 4) & 1) * 8;
        int bkb  = ((lane >> 3) & 1) * 8;
#pragma unroll
        for (int ng = 0; ng < 4; ng++) {
            uint32_t boff = (uint32_t)((wn * 64 + ng * 16 + brow) * 48 + bkb * 2);
            uint32_t Sh4[4], Sl4[4];
            LDM_X4(Sh4[0], Sh4[1], Sh4[2], Sh4[3], base + 4 * M_ARR + boff);
            LDM_X4(Sl4[0], Sl4[1], Sl4[2], Sl4[3], base + 5 * M_ARR + boff);
#pragma unroll
            for (int ct = 0; ct < 2; ct++) {
#pragma unroll
                for (int sub = 0; sub < 2; sub++) {
                    uint32_t s0 = Sh4[2 * sub], s1 = Sh4[2 * sub + 1];
                    uint32_t t0 = Sl4[2 * sub], t1 = Sl4[2 * sub + 1];
                    float* pm = dm[ct][2 * ng + sub];
                    float* pe = de[ct][2 * ng + sub];
                    mma16816(pm, Hh[ct], s0, s1);
                    mma16816(pe, Wh[ct], s0, s1);
                    mma16816(pm, Hh[ct], t0, t1);
                    mma16816(pe, Wh[ct], t0, t1);
                    mma16816(pm, Hl[ct], s0, s1);
                    mma16816(pe, Wl[ct], s0, s1);
                }
            }
        }
        __syncthreads();
    }

    // Fused epilogue: out[b][c][n] = sqrt(relu(e2 - mean^2)) * c_x + mean
#pragma unroll
    for (int ct = 0; ct < 2; ct++)
#pragma unroll
        for (int j = 0; j < 8; j++) {
            int cbase = cc0 + wc * 32 + ct * 16 + (lane >> 2);
            int n = n0 + wn * 64 + j * 8 + (lane & 3) * 2;
#pragma unroll
            for (int rr = 0; rr < 2; rr++) {
                int cr = cbase + rr * 8;
                float m0v = dm[ct][j][2 * rr],     e0 = de[ct][j][2 * rr];
                float m1v = dm[ct][j][2 * rr + 1], e1 = de[ct][j][2 * rr + 1];
                size_t idx = ((size_t)b * CC + cr) * NP + n;
                float2 cx = *reinterpret_cast<const float2*>(&c_x[idx]);
                float sd0 = sqrtf(fmaxf(e0 - m0v * m0v, 0.f));
                float sd1 = sqrtf(fmaxf(e1 - m1v * m1v, 0.f));
                *reinterpret_cast<float2*>(&out[idx]) =
                    make_float2(sd0 * cx.x + m0v, sd1 * cx.y + m1v);
            }
        }
}

// ============================================================================
// Launch
// ============================================================================
extern "C" void kernel_launch(void* const* d_in, const int* in_sizes, int n_in,
                              void* d_out, int out_size)
{
    const float* c_x  = (const float*)d_in[0];
    const float* s_x  = (const float*)d_in[1];
    const float* c_1x = (const float*)d_in[2];
    const float* s_1x = (const float*)d_in[3];
    const float* f_w  = (const float*)d_in[4];
    const float* f_b  = (const float*)d_in[5];
    const float* g_w  = (const float*)d_in[6];
    const float* g_b  = (const float*)d_in[7];
    const float* h_w  = (const float*)d_in[8];
    const float* h_b  = (const float*)d_in[9];
    float* out = (float*)d_out;

    (void)in_sizes; (void)n_in; (void)out_size;

    static int attr_done = 0;
    if (!attr_done) {
        cudaFuncSetAttribute(conv_nk,
                             cudaFuncAttributeMaxDynamicSharedMemorySize, P_SMEM);
        cudaFuncSetAttribute(conv_cm,
                             cudaFuncAttributeMaxDynamicSharedMemorySize, P_SMEM);
        cudaFuncSetAttribute(logits_hmma,
                             cudaFuncAttributeMaxDynamicSharedMemorySize, P_SMEM);
        cudaFuncSetAttribute(meanstd_hmma,
                             cudaFuncAttributeMaxDynamicSharedMemorySize, M_SMEM);
        attr_done = 1;
    }

    dim3 gridT(NP / 32, KPD / 32, NB);     // split_xt: (128, 16, 4)
    dim3 gridC(NP / 128, KPD / 128, NB);   // convs: (32, 4, 4)

    // F = f(c_1x)
    split_wk<<<512, 256>>>(f_w);
    split_xt<<<gridT, 256>>>(c_1x);
    conv_nk<<<gridC, 256, P_SMEM>>>(f_b, 0);

    // G = g(s_1x)
    split_wk<<<512, 256>>>(g_w);
    split_xt<<<gridT, 256>>>(s_1x);
    conv_nk<<<gridC, 256, P_SMEM>>>(g_b, 1);

    // Ht (+ Ht^2) = h(s_x), transposed output
    split_wk<<<512, 256>>>(h_w);
    split_xt<<<gridT, 256>>>(s_x);
    conv_cm<<<gridC, 256, P_SMEM>>>(h_b);

    dim3 gridL(MP / 128, NP / 128, NB);    // (32, 32, 4)
    logits_hmma<<<gridL, 256, P_SMEM>>>();

    softmax_rows<<<NB * NP, 256>>>();      // 16384 rows

    dim3 gridM(NP / 128, CC / 128, NB);    // (32, 4, 4)
    meanstd_hmma<<<gridM, 256, M_SMEM>>>(c_x, out);
}

// round 16
// speedup vs baseline: 1.1391x; 1.1391x over previous
#include <cuda_runtime.h>
#include <cuda_bf16.h>
#include <math.h>
#include <stdint.h>

// Problem constants
#define NB 4          // batch
#define CC 512        // channels C
#define KPD 512       // key planes
#define NP 4096       // H*W
#define MP 4096       // HS*WS

// ============================================================================
// bf16 split helpers
// ============================================================================
__device__ __forceinline__ uint32_t bpack2(float v0, float v1,
                                           uint32_t& lo_out) {
    __nv_bfloat16 h0 = __float2bfloat16(v0);
    __nv_bfloat16 h1 = __float2bfloat16(v1);
    __nv_bfloat16 l0 = __float2bfloat16(v0 - __bfloat162float(h0));
    __nv_bfloat16 l1 = __float2bfloat16(v1 - __bfloat162float(h1));
    uint16_t uh0 = *reinterpret_cast<uint16_t*>(&h0);
    uint16_t uh1 = *reinterpret_cast<uint16_t*>(&h1);
    uint16_t ul0 = *reinterpret_cast<uint16_t*>(&l0);
    uint16_t ul1 = *reinterpret_cast<uint16_t*>(&l1);
    lo_out = (uint32_t)ul0 | ((uint32_t)ul1 << 16);
    return (uint32_t)uh0 | ((uint32_t)uh1 << 16);
}

// ============================================================================
// HMMA / ldmatrix / cp.async (portable sm_80+ PTX — valid on plain sm_103)
// ============================================================================
__device__ __forceinline__ uint32_t smem_u32(const void* p) {
    uint32_t a;
    asm("{ .reg .u64 t; cvta.to.shared.u64 t, %1; cvt.u32.u64 %0, t; }"
        : "=r"(a) : "l"(p));
    return a;
}

#define LDM_X4(r0, r1, r2, r3, a) \
    asm volatile("ldmatrix.sync.aligned.m8n8.x4.shared.b16 {%0,%1,%2,%3}, [%4];" \
                 : "=r"(r0), "=r"(r1), "=r"(r2), "=r"(r3) : "r"(a))

__device__ __forceinline__ void mma16816(float* d, const uint32_t* a,
                                         uint32_t b0, uint32_t b1) {
    asm volatile(
        "mma.sync.aligned.m16n8k16.row.col.f32.bf16.bf16.f32 "
        "{%0,%1,%2,%3}, {%4,%5,%6,%7}, {%8,%9}, {%0,%1,%2,%3};"
        : "+f"(d[0]), "+f"(d[1]), "+f"(d[2]), "+f"(d[3])
        : "r"(a[0]), "r"(a[1]), "r"(a[2]), "r"(a[3]), "r"(b0), "r"(b1));
}

#define CP_ASYNC16(dst, src) \
    asm volatile("cp.async.cg.shared.global [%0], [%1], 16;" \
                 :: "r"(dst), "l"(src))
#define CP_COMMIT() asm volatile("cp.async.commit_group;" ::: "memory")
#define CP_WAIT0()  asm volatile("cp.async.wait_group 0;" ::: "memory")
#define CP_WAIT1()  asm volatile("cp.async.wait_group 1;" ::: "memory")

// ============================================================================
// Device-global scratch (alloc-free per harness rules)
// ============================================================================
__device__ float g_S[(size_t)NB * NP * MP];              // logits f32
__device__ __nv_bfloat16 g_Fh[(size_t)NB * NP * KPD];    // F [b][n][k] hi
__device__ __nv_bfloat16 g_Fl[(size_t)NB * NP * KPD];
__device__ __nv_bfloat16 g_Gh[(size_t)NB * MP * KPD];    // G [b][m][k]
__device__ __nv_bfloat16 g_Gl[(size_t)NB * MP * KPD];
__device__ __nv_bfloat16 g_Hth[(size_t)NB * CC * MP];    // Ht [b][c][m]
__device__ __nv_bfloat16 g_Htl[(size_t)NB * CC * MP];
__device__ __nv_bfloat16 g_Qh [(size_t)NB * CC * MP];    // Ht^2 [b][c][m]
__device__ __nv_bfloat16 g_Ql [(size_t)NB * CC * MP];
__device__ __nv_bfloat16 g_Sh[(size_t)NB * NP * MP];     // softmax probs
__device__ __nv_bfloat16 g_Sl[(size_t)NB * NP * MP];
// Conv staging (reused sequentially for c_1x, s_1x, s_x)
__device__ __nv_bfloat16 g_Xth[(size_t)NB * NP * KPD];   // X^T [b][i][k] hi
__device__ __nv_bfloat16 g_Xtl[(size_t)NB * NP * KPD];
__device__ __nv_bfloat16 g_Wh[(size_t)KPD * KPD];        // W [j][k] hi
__device__ __nv_bfloat16 g_Wl[(size_t)KPD * KPD];

// ============================================================================
// Split / transpose kernels
// ============================================================================
__global__ void __launch_bounds__(256)
split_xt(const float* __restrict__ X)
{
    __shared__ float tile[32][33];
    int b = blockIdx.z;
    int i0 = blockIdx.x * 32, k0 = blockIdx.y * 32;
    int tx = threadIdx.x & 31, ty = threadIdx.x >> 5;   // ty 0..7
    const float* Xb = X + (size_t)b * KPD * NP;
#pragma unroll
    for (int r = 0; r < 4; r++) {
        int k = ty + r * 8;
        tile[k][tx] = Xb[(size_t)(k0 + k) * NP + i0 + tx];
    }
    __syncthreads();
    size_t ob = (size_t)b * NP * KPD;
#pragma unroll
    for (int r = 0; r < 4; r++) {
        int i = ty + r * 8;
        float v = tile[tx][i];
        __nv_bfloat16 h = __float2bfloat16(v);
        __nv_bfloat16 l = __float2bfloat16(v - __bfloat162float(h));
        size_t idx = ob + (size_t)(i0 + i) * KPD + k0 + tx;
        g_Xth[idx] = h;
        g_Xtl[idx] = l;
    }
}

__global__ void __launch_bounds__(256)
split_wk(const float* __restrict__ W)
{
    int idx = blockIdx.x * 256 + threadIdx.x;   // each handles 2 floats
    float2 v = reinterpret_cast<const float2*>(W)[idx];
    uint32_t lo;
    uint32_t hi = bpack2(v.x, v.y, lo);
    reinterpret_cast<uint32_t*>(g_Wh)[idx] = hi;
    reinterpret_cast<uint32_t*>(g_Wl)[idx] = lo;
}

// ============================================================================
// Pipeline geometry (KC = 32, 80B row stride — proven R14 config)
// ============================================================================
#define P_ARR  10240
#define P_STG  (4 * P_ARR)
#define P_SMEM (2 * P_STG)      // 81920 -> 2 CTAs/SM

// meanstd: A-side (H/Q) keeps stride 80; S arrays use stride 64 (no pad) to
// fit the 2-CTA/SM smem budget (4*10240 + 2*8192 = 57344/stage, 114688 total).
#define M_ARR_A 10240
#define M_ARR_S 8192
#define M_SOFF  (4 * M_ARR_A)            // S arrays start offset within stage
#define M_STG   (4 * M_ARR_A + 2 * M_ARR_S)
#define M_SMEM  (2 * M_STG)              // 114688 -> 2 CTAs/SM

// ============================================================================
// Core 128x128 3-term mainloop for one KC=32 stage (two k16 chunks).
// ============================================================================
__device__ __forceinline__ void hmma_mainloop_stage(uint32_t base, int lane,
                                                    int wn, int wm,
                                                    float d[2][8][4])
{
    int r8 = lane & 7;
#pragma unroll
    for (int ks = 0; ks < 2; ks++) {
        uint32_t Ah[2][4], Al[2][4];
        int arow = r8 + ((lane >> 3) & 1) * 8;
        int akb  = ks * 16 + ((lane >> 4) & 1) * 8;
#pragma unroll
        for (int nt = 0; nt < 2; nt++) {
            uint32_t aoff = (uint32_t)((wn * 32 + nt * 16 + arow) * 80 + akb * 2);
            LDM_X4(Ah[nt][0], Ah[nt][1], Ah[nt][2], Ah[nt][3], base + 0 * P_ARR + aoff);
            LDM_X4(Al[nt][0], Al[nt][1], Al[nt][2], Al[nt][3], base + 1 * P_ARR + aoff);
        }
        int brow = r8 + ((lane >> 4) & 1) * 8;
        int bkb  = ks * 16 + ((lane >> 3) & 1) * 8;
#pragma unroll
        for (int mg = 0; mg < 4; mg++) {
            uint32_t boff = (uint32_t)((wm * 64 + mg * 16 + brow) * 80 + bkb * 2);
            uint32_t Bh[4], Bl[4];
            LDM_X4(Bh[0], Bh[1], Bh[2], Bh[3], base + 2 * P_ARR + boff);
            LDM_X4(Bl[0], Bl[1], Bl[2], Bl[3], base + 3 * P_ARR + boff);
#pragma unroll
            for (int nt = 0; nt < 2; nt++) {
                float* p0 = d[nt][2 * mg];
                float* p1 = d[nt][2 * mg + 1];
                mma16816(p0, Ah[nt], Bh[0], Bh[1]);
                mma16816(p0, Ah[nt], Bl[0], Bl[1]);
                mma16816(p0, Al[nt], Bh[0], Bh[1]);
                mma16816(p1, Ah[nt], Bh[2], Bh[3]);
                mma16816(p1, Ah[nt], Bl[2], Bl[3]);
                mma16816(p1, Al[nt], Bh[2], Bh[3]);
            }
        }
    }
}

// ============================================================================
// Conv GEMM via HMMA. stages = KPD/32 = 16.
// ============================================================================
#define C_STAGES (KPD / 32)

__device__ __forceinline__ void conv_issue(int s, uint32_t sb, int tid,
                                           size_t xb, int a0, int b0, int swap)
{
    uint32_t base = sb + (uint32_t)(s & 1) * P_STG;
    int k0 = s * 32;
#pragma unroll
    for (int q = 0; q < 8; q++) {
        int id = q * 256 + tid;
        int arr = id >> 9, rem = id & 511, row = rem >> 2, c = rem & 3;
        const __nv_bfloat16* src;
        if (!swap) {
            if (arr == 0)      src = g_Xth + xb + (size_t)(a0 + row) * KPD + k0 + c * 8;
            else if (arr == 1) src = g_Xtl + xb + (size_t)(a0 + row) * KPD + k0 + c * 8;
            else if (arr == 2) src = g_Wh + (size_t)(b0 + row) * KPD + k0 + c * 8;
            else               src = g_Wl + (size_t)(b0 + row) * KPD + k0 + c * 8;
        } else {
            if (arr == 0)      src = g_Wh + (size_t)(a0 + row) * KPD + k0 + c * 8;
            else if (arr == 1) src = g_Wl + (size_t)(a0 + row) * KPD + k0 + c * 8;
            else if (arr == 2) src = g_Xth + xb + (size_t)(b0 + row) * KPD + k0 + c * 8;
            else               src = g_Xtl + xb + (size_t)(b0 + row) * KPD + k0 + c * 8;
        }
        uint32_t dst = base + (uint32_t)arr * P_ARR + row * 80 + c * 16;
        CP_ASYNC16(dst, (const void*)src);
    }
    CP_COMMIT();
}

// dest 0 -> F, 1 -> G: output [n][k] split, bias over columns
__global__ void __launch_bounds__(256)
conv_nk(const float* __restrict__ bias, int dest)
{
    extern __shared__ char sm[];
    uint32_t sb = smem_u32(sm);
    int tid = threadIdx.x, lane = tid & 31, warp = tid >> 5;
    int wn = warp >> 1, wm = warp & 1;
    int b = blockIdx.z, i0 = blockIdx.x * 128, j0 = blockIdx.y * 128;
    size_t xb = (size_t)b * NP * KPD;

    float d[2][8][4];
#pragma unroll
    for (int a = 0; a < 2; a++)
#pragma unroll
        for (int j = 0; j < 8; j++)
#pragma unroll
            for (int r = 0; r < 4; r++) d[a][j][r] = 0.f;

    conv_issue(0, sb, tid, xb, i0, j0, 0);
    for (int s = 0; s < C_STAGES; s++) {
        if (s + 1 < C_STAGES) { conv_issue(s + 1, sb, tid, xb, i0, j0, 0); CP_WAIT1(); }
        else                  { CP_WAIT0(); }
        __syncthreads();
        hmma_mainloop_stage(sb + (uint32_t)(s & 1) * P_STG, lane, wn, wm, d);
        __syncthreads();
    }

    size_t bb = (size_t)b * NP * KPD;
    __nv_bfloat16* Dh = (dest == 0 ? g_Fh : g_Gh) + bb;
    __nv_bfloat16* Dl = (dest == 0 ? g_Fl : g_Gl) + bb;
#pragma unroll
    for (int nt = 0; nt < 2; nt++)
#pragma unroll
        for (int m8 = 0; m8 < 8; m8++) {
            int n = i0 + wn * 32 + nt * 16 + (lane >> 2);
            int j = j0 + wm * 64 + m8 * 8 + (lane & 3) * 2;
            float2 bv = *reinterpret_cast<const float2*>(&bias[j]);
            uint32_t lo, hi;
            hi = bpack2(d[nt][m8][0] + bv.x, d[nt][m8][1] + bv.y, lo);
            *reinterpret_cast<uint32_t*>(Dh + (size_t)n * KPD + j) = hi;
            *reinterpret_cast<uint32_t*>(Dl + (size_t)n * KPD + j) = lo;
            hi = bpack2(d[nt][m8][2] + bv.x, d[nt][m8][3] + bv.y, lo);
            *reinterpret_cast<uint32_t*>(Dh + (size_t)(n + 8) * KPD + j) = hi;
            *reinterpret_cast<uint32_t*>(Dl + (size_t)(n + 8) * KPD + j) = lo;
        }
}

// Ht conv: output rows = channels -> Ht [c][m] and Ht^2 [c][m] splits
__global__ void __launch_bounds__(256)
conv_cm(const float* __restrict__ bias)
{
    extern __shared__ char sm[];
    uint32_t sb = smem_u32(sm);
    int tid = threadIdx.x, lane = tid & 31, warp = tid >> 5;
    int wc = warp >> 1, wm = warp & 1;
    int b = blockIdx.z, m0 = blockIdx.x * 128, c0 = blockIdx.y * 128;
    size_t xb = (size_t)b * NP * KPD;

    float d[2][8][4];
#pragma unroll
    for (int a = 0; a < 2; a++)
#pragma unroll
        for (int j = 0; j < 8; j++)
#pragma unroll
            for (int r = 0; r < 4; r++) d[a][j][r] = 0.f;

    conv_issue(0, sb, tid, xb, c0, m0, 1);
    for (int s = 0; s < C_STAGES; s++) {
        if (s + 1 < C_STAGES) { conv_issue(s + 1, sb, tid, xb, c0, m0, 1); CP_WAIT1(); }
        else                  { CP_WAIT0(); }
        __syncthreads();
        hmma_mainloop_stage(sb + (uint32_t)(s & 1) * P_STG, lane, wc, wm, d);
        __syncthreads();
    }

    size_t bb = (size_t)b * CC * MP;
#pragma unroll
    for (int ct = 0; ct < 2; ct++)
#pragma unroll
        for (int m8 = 0; m8 < 8; m8++) {
            int c = c0 + wc * 32 + ct * 16 + (lane >> 2);
            int m = m0 + wm * 64 + m8 * 8 + (lane & 3) * 2;
            float b0v = bias[c], b1v = bias[c + 8];
            float v0 = d[ct][m8][0] + b0v, v1 = d[ct][m8][1] + b0v;
            float v2 = d[ct][m8][2] + b1v, v3 = d[ct][m8][3] + b1v;
            size_t idx0 = bb + (size_t)c * MP + m;
            size_t idx1 = bb + (size_t)(c + 8) * MP + m;
            uint32_t lo, hi;
            hi = bpack2(v0, v1, lo);
            *reinterpret_cast<uint32_t*>(g_Hth + idx0) = hi;
            *reinterpret_cast<uint32_t*>(g_Htl + idx0) = lo;
            hi = bpack2(v0 * v0, v1 * v1, lo);
            *reinterpret_cast<uint32_t*>(g_Qh + idx0) = hi;
            *reinterpret_cast<uint32_t*>(g_Ql + idx0) = lo;
            hi = bpack2(v2, v3, lo);
            *reinterpret_cast<uint32_t*>(g_Hth + idx1) = hi;
            *reinterpret_cast<uint32_t*>(g_Htl + idx1) = lo;
            hi = bpack2(v2 * v2, v3 * v3, lo);
            *reinterpret_cast<uint32_t*>(g_Qh + idx1) = hi;
            *reinterpret_cast<uint32_t*>(g_Ql + idx1) = lo;
        }
}

// ============================================================================
// Logits GEMM via HMMA. stages = KPD/32 = 16.
// ============================================================================
#define L_STAGES (KPD / 32)

__device__ __forceinline__ void logits_issue(int s, uint32_t sb, int tid,
                                             int b, int n0, int m0)
{
    uint32_t base = sb + (uint32_t)(s & 1) * P_STG;
    int k0 = s * 32;
    size_t fb = (size_t)b * NP * KPD;
    size_t gb = (size_t)b * MP * KPD;
#pragma unroll
    for (int q = 0; q < 8; q++) {
        int id = q * 256 + tid;
        int arr = id >> 9, rem = id & 511, row = rem >> 2, c = rem & 3;
        const __nv_bfloat16* src;
        if (arr == 0)      src = g_Fh + fb + (size_t)(n0 + row) * KPD + k0 + c * 8;
        else if (arr == 1) src = g_Fl + fb + (size_t)(n0 + row) * KPD + k0 + c * 8;
        else if (arr == 2) src = g_Gh + gb + (size_t)(m0 + row) * KPD + k0 + c * 8;
        else               src = g_Gl + gb + (size_t)(m0 + row) * KPD + k0 + c * 8;
        uint32_t dst = base + (uint32_t)arr * P_ARR + row * 80 + c * 16;
        CP_ASYNC16(dst, (const void*)src);
    }
    CP_COMMIT();
}

__global__ void __launch_bounds__(256)
logits_hmma()
{
    extern __shared__ char sm[];
    uint32_t sb = smem_u32(sm);
    int tid = threadIdx.x, lane = tid & 31, warp = tid >> 5;
    int wn = warp >> 1, wm = warp & 1;
    int b = blockIdx.z, m0 = blockIdx.x * 128, n0 = blockIdx.y * 128;
    float* Sb = g_S + (size_t)b * NP * MP;

    float d[2][8][4];
#pragma unroll
    for (int a = 0; a < 2; a++)
#pragma unroll
        for (int j = 0; j < 8; j++)
#pragma unroll
            for (int r = 0; r < 4; r++) d[a][j][r] = 0.f;

    logits_issue(0, sb, tid, b, n0, m0);
    for (int s = 0; s < L_STAGES; s++) {
        if (s + 1 < L_STAGES) { logits_issue(s + 1, sb, tid, b, n0, m0); CP_WAIT1(); }
        else                  { CP_WAIT0(); }
        __syncthreads();
        hmma_mainloop_stage(sb + (uint32_t)(s & 1) * P_STG, lane, wn, wm, d);
        __syncthreads();
    }

#pragma unroll
    for (int nt = 0; nt < 2; nt++)
#pragma unroll
        for (int m8 = 0; m8 < 8; m8++) {
            int n = n0 + wn * 32 + nt * 16 + (lane >> 2);
            int m = m0 + wm * 64 + m8 * 8 + (lane & 3) * 2;
            *reinterpret_cast<float2*>(&Sb[(size_t)n * MP + m]) =
                make_float2(d[nt][m8][0], d[nt][m8][1]);
            *reinterpret_cast<float2*>(&Sb[(size_t)(n + 8) * MP + m]) =
                make_float2(d[nt][m8][2], d[nt][m8][3]);
        }
}

// ============================================================================
// Row softmax: f32 logits -> bf16 hi/lo probabilities.
// ============================================================================
__global__ void __launch_bounds__(256)
softmax_rows()
{
    __shared__ float red[256];
    int row = blockIdx.x;
    size_t base = (size_t)row * MP;
    int tid = threadIdx.x;

    float2 v[8];
    float lmax = -1e30f;
#pragma unroll
    for (int t = 0; t < 8; t++) {
        v[t] = *reinterpret_cast<const float2*>(&g_S[base + tid * 2 + t * 512]);
        lmax = fmaxf(lmax, fmaxf(v[t].x, v[t].y));
    }
    red[tid] = lmax;
    __syncthreads();
    for (int s = 128; s > 0; s >>= 1) {
        if (tid < s) red[tid] = fmaxf(red[tid], red[tid + s]);
        __syncthreads();
    }
    float m = red[0];
    __syncthreads();

    float lsum = 0.f;
#pragma unroll
    for (int t = 0; t < 8; t++) {
        v[t].x = __expf(v[t].x - m);
        v[t].y = __expf(v[t].y - m);
        lsum += v[t].x + v[t].y;
    }
    red[tid] = lsum;
    __syncthreads();
    for (int s = 128; s > 0; s >>= 1) {
        if (tid < s) red[tid] += red[tid + s];
        __syncthreads();
    }
    float inv = 1.f / red[0];

#pragma unroll
    for (int t = 0; t < 8; t++) {
        size_t idx = base + tid * 2 + t * 512;
        uint32_t lo;
        uint32_t hi = bpack2(v[t].x * inv, v[t].y * inv, lo);
        *reinterpret_cast<uint32_t*>(&g_Sh[idx]) = hi;
        *reinterpret_cast<uint32_t*>(&g_Sl[idx]) = lo;
    }
}

// ============================================================================
// Dual GEMM (mean & e2) + fused epilogue. stages = MP/32 = 128.
// A-side arrays stride 80 (conflict-free); S arrays stride 64 (fits 2 CTA/SM).
// ============================================================================
#define M_STAGES (MP / 32)

__device__ __forceinline__ void meanstd_issue(int s, uint32_t sb, int tid,
                                              int b, int cc0, int n0)
{
    uint32_t base = sb + (uint32_t)(s & 1) * M_STG;
    int mm = s * 32;
    size_t hb = (size_t)b * CC * MP;
    size_t pb = (size_t)b * NP * MP;
#pragma unroll
    for (int q = 0; q < 12; q++) {
        int id = q * 256 + tid;
        int arr = id >> 9, rem = id & 511, row = rem >> 2, c = rem & 3;
        const __nv_bfloat16* src;
        uint32_t dst;
        if (arr == 0) {
            src = g_Hth + hb + (size_t)(cc0 + row) * MP + mm + c * 8;
            dst = base + 0 * M_ARR_A + row * 80 + c * 16;
        } else if (arr == 1) {
            src = g_Htl + hb + (size_t)(cc0 + row) * MP + mm + c * 8;
            dst = base + 1 * M_ARR_A + row * 80 + c * 16;
        } else if (arr == 2) {
            src = g_Qh + hb + (size_t)(cc0 + row) * MP + mm + c * 8;
            dst = base + 2 * M_ARR_A + row * 80 + c * 16;
        } else if (arr == 3) {
            src = g_Ql + hb + (size_t)(cc0 + row) * MP + mm + c * 8;
            dst = base + 3 * M_ARR_A + row * 80 + c * 16;
        } else if (arr == 4) {
            src = g_Sh + pb + (size_t)(n0 + row) * MP + mm + c * 8;
            dst = base + M_SOFF + row * 64 + c * 16;
        } else {
            src = g_Sl + pb + (size_t)(n0 + row) * MP + mm + c * 8;
            dst = base + M_SOFF + M_ARR_S + row * 64 + c * 16;
        }
        CP_ASYNC16(dst, (const void*)src);
    }
    CP_COMMIT();
}

__global__ void __launch_bounds__(256)
meanstd_hmma(const float* __restrict__ c_x, float* __restrict__ out)
{
    extern __shared__ char sm[];
    uint32_t sb = smem_u32(sm);
    int tid = threadIdx.x, lane = tid & 31, warp = tid >> 5;
    int wc = warp >> 1, wn = warp & 1;
    int b = blockIdx.z, n0 = blockIdx.x * 128, cc0 = blockIdx.y * 128;

    float dm[2][8][4], de[2][8][4];
#pragma unroll
    for (int a = 0; a < 2; a++)
#pragma unroll
        for (int j = 0; j < 8; j++)
#pragma unroll
            for (int r = 0; r < 4; r++) { dm[a][j][r] = 0.f; de[a][j][r] = 0.f; }

    meanstd_issue(0, sb, tid, b, cc0, n0);

    int r8 = lane & 7;
    for (int s = 0; s < M_STAGES; s++) {
        if (s + 1 < M_STAGES) { meanstd_issue(s + 1, sb, tid, b, cc0, n0); CP_WAIT1(); }
        else                  { CP_WAIT0(); }
        __syncthreads();

        uint32_t base = sb + (uint32_t)(s & 1) * M_STG;
#pragma unroll
        for (int ks = 0; ks < 2; ks++) {
            uint32_t Hh[2][4], Hl[2][4], Wh[2][4], Wl[2][4];
            int arow = r8 + ((lane >> 3) & 1) * 8;
            int akb  = ks * 16 + ((lane >> 4) & 1) * 8;
#pragma unroll
            for (int ct = 0; ct < 2; ct++) {
                uint32_t aoff = (uint32_t)((wc * 32 + ct * 16 + arow) * 80 + akb * 2);
                LDM_X4(Hh[ct][0], Hh[ct][1], Hh[ct][2], Hh[ct][3], base + 0 * M_ARR_A + aoff);
                LDM_X4(Hl[ct][0], Hl[ct][1], Hl[ct][2], Hl[ct][3], base + 1 * M_ARR_A + aoff);
                LDM_X4(Wh[ct][0], Wh[ct][1], Wh[ct][2], Wh[ct][3], base + 2 * M_ARR_A + aoff);
                LDM_X4(Wl[ct][0], Wl[ct][1], Wl[ct][2], Wl[ct][3], base + 3 * M_ARR_A + aoff);
            }
            int brow = r8 + ((lane >> 4) & 1) * 8;
            int bkb  = ks * 16 + ((lane >> 3) & 1) * 8;
#pragma unroll
            for (int ng = 0; ng < 4; ng++) {
                uint32_t boff = (uint32_t)((wn * 64 + ng * 16 + brow) * 64 + bkb * 2);
                uint32_t Sh4[4], Sl4[4];
                LDM_X4(Sh4[0], Sh4[1], Sh4[2], Sh4[3], base + M_SOFF + boff);
                LDM_X4(Sl4[0], Sl4[1], Sl4[2], Sl4[3], base + M_SOFF + M_ARR_S + boff);
#pragma unroll
                for (int ct = 0; ct < 2; ct++) {
#pragma unroll
                    for (int sub = 0; sub < 2; sub++) {
                        uint32_t s0 = Sh4[2 * sub], s1 = Sh4[2 * sub + 1];
                        uint32_t t0 = Sl4[2 * sub], t1 = Sl4[2 * sub + 1];
                        float* pm = dm[ct][2 * ng + sub];
                        float* pe = de[ct][2 * ng + sub];
                        mma16816(pm, Hh[ct], s0, s1);
                        mma16816(pm, Hh[ct], t0, t1);
                        mma16816(pm, Hl[ct], s0, s1);
                        mma16816(pe, Wh[ct], s0, s1);
                        mma16816(pe, Wh[ct], t0, t1);
                        mma16816(pe, Wl[ct], s0, s1);
                    }
                }
            }
        }
        __syncthreads();
    }

    // Fused epilogue: out[b][c][n] = sqrt(relu(e2 - mean^2)) * c_x + mean
#pragma unroll
    for (int ct = 0; ct < 2; ct++)
#pragma unroll
        for (int j = 0; j < 8; j++) {
            int cbase = cc0 + wc * 32 + ct * 16 + (lane >> 2);
            int n = n0 + wn * 64 + j * 8 + (lane & 3) * 2;
#pragma unroll
            for (int rr = 0; rr < 2; rr++) {
                int cr = cbase + rr * 8;
                float m0v = dm[ct][j][2 * rr],     e0 = de[ct][j][2 * rr];
                float m1v = dm[ct][j][2 * rr + 1], e1 = de[ct][j][2 * rr + 1];
                size_t idx = ((size_t)b * CC + cr) * NP + n;
                float2 cx = *reinterpret_cast<const float2*>(&c_x[idx]);
                float sd0 = sqrtf(fmaxf(e0 - m0v * m0v, 0.f));
                float sd1 = sqrtf(fmaxf(e1 - m1v * m1v, 0.f));
                *reinterpret_cast<float2*>(&out[idx]) =
                    make_float2(sd0 * cx.x + m0v, sd1 * cx.y + m1v);
            }
        }
}

// ============================================================================
// Launch
// ============================================================================
extern "C" void kernel_launch(void* const* d_in, const int* in_sizes, int n_in,
                              void* d_out, int out_size)
{
    const float* c_x  = (const float*)d_in[0];
    const float* s_x  = (const float*)d_in[1];
    const float* c_1x = (const float*)d_in[2];
    const float* s_1x = (const float*)d_in[3];
    const float* f_w  = (const float*)d_in[4];
    const float* f_b  = (const float*)d_in[5];
    const float* g_w  = (const float*)d_in[6];
    const float* g_b  = (const float*)d_in[7];
    const float* h_w  = (const float*)d_in[8];
    const float* h_b  = (const float*)d_in[9];
    float* out = (float*)d_out;

    (void)in_sizes; (void)n_in; (void)out_size;

    static int attr_done = 0;
    if (!attr_done) {
        cudaFuncSetAttribute(conv_nk,
                             cudaFuncAttributeMaxDynamicSharedMemorySize, P_SMEM);
        cudaFuncSetAttribute(conv_cm,
                             cudaFuncAttributeMaxDynamicSharedMemorySize, P_SMEM);
        cudaFuncSetAttribute(logits_hmma,
                             cudaFuncAttributeMaxDynamicSharedMemorySize, P_SMEM);
        cudaFuncSetAttribute(meanstd_hmma,
                             cudaFuncAttributeMaxDynamicSharedMemorySize, M_SMEM);
        attr_done = 1;
    }

    dim3 gridT(NP / 32, KPD / 32, NB);     // split_xt: (128, 16, 4)
    dim3 gridC(NP / 128, KPD / 128, NB);   // convs: (32, 4, 4)

    // F = f(c_1x)
    split_wk<<<512, 256>>>(f_w);
    split_xt<<<gridT, 256>>>(c_1x);
    conv_nk<<<gridC, 256, P_SMEM>>>(f_b, 0);

    // G = g(s_1x)
    split_wk<<<512, 256>>>(g_w);
    split_xt<<<gridT, 256>>>(s_1x);
    conv_nk<<<gridC, 256, P_SMEM>>>(g_b, 1);

    // Ht (+ Ht^2) = h(s_x), transposed output
    split_wk<<<512, 256>>>(h_w);
    split_xt<<<gridT, 256>>>(s_x);
    conv_cm<<<gridC, 256, P_SMEM>>>(h_b);

    dim3 gridL(MP / 128, NP / 128, NB);    // (32, 32, 4)
    logits_hmma<<<gridL, 256, P_SMEM>>>();

    softmax_rows<<<NB * NP, 256>>>();      // 16384 rows

    dim3 gridM(NP / 128, CC / 128, NB);    // (32, 4, 4)
    meanstd_hmma<<<gridM, 256, M_SMEM>>>(c_x, out);
}

// round 17
// speedup vs baseline: 1.2304x; 1.0801x over previous
#include <cuda_runtime.h>
#include <cuda_bf16.h>
#include <math.h>
#include <stdint.h>

// Problem constants
#define NB 4          // batch
#define CC 512        // channels C
#define KPD 512       // key planes
#define NP 4096       // H*W
#define MP 4096       // HS*WS

// ============================================================================
// bf16 split helpers
// ============================================================================
__device__ __forceinline__ uint32_t bpack2(float v0, float v1,
                                           uint32_t& lo_out) {
    __nv_bfloat16 h0 = __float2bfloat16(v0);
    __nv_bfloat16 h1 = __float2bfloat16(v1);
    __nv_bfloat16 l0 = __float2bfloat16(v0 - __bfloat162float(h0));
    __nv_bfloat16 l1 = __float2bfloat16(v1 - __bfloat162float(h1));
    uint16_t uh0 = *reinterpret_cast<uint16_t*>(&h0);
    uint16_t uh1 = *reinterpret_cast<uint16_t*>(&h1);
    uint16_t ul0 = *reinterpret_cast<uint16_t*>(&l0);
    uint16_t ul1 = *reinterpret_cast<uint16_t*>(&l1);
    lo_out = (uint32_t)ul0 | ((uint32_t)ul1 << 16);
    return (uint32_t)uh0 | ((uint32_t)uh1 << 16);
}

// ============================================================================
// HMMA / ldmatrix / cp.async (portable sm_80+ PTX — valid on plain sm_103)
// ============================================================================
__device__ __forceinline__ uint32_t smem_u32(const void* p) {
    uint32_t a;
    asm("{ .reg .u64 t; cvta.to.shared.u64 t, %1; cvt.u32.u64 %0, t; }"
        : "=r"(a) : "l"(p));
    return a;
}

#define LDM_X4(r0, r1, r2, r3, a) \
    asm volatile("ldmatrix.sync.aligned.m8n8.x4.shared.b16 {%0,%1,%2,%3}, [%4];" \
                 : "=r"(r0), "=r"(r1), "=r"(r2), "=r"(r3) : "r"(a))

__device__ __forceinline__ void mma16816(float* d, const uint32_t* a,
                                         uint32_t b0, uint32_t b1) {
    asm volatile(
        "mma.sync.aligned.m16n8k16.row.col.f32.bf16.bf16.f32 "
        "{%0,%1,%2,%3}, {%4,%5,%6,%7}, {%8,%9}, {%0,%1,%2,%3};"
        : "+f"(d[0]), "+f"(d[1]), "+f"(d[2]), "+f"(d[3])
        : "r"(a[0]), "r"(a[1]), "r"(a[2]), "r"(a[3]), "r"(b0), "r"(b1));
}

#define CP_ASYNC16(dst, src) \
    asm volatile("cp.async.cg.shared.global [%0], [%1], 16;" \
                 :: "r"(dst), "l"(src))
#define CP_COMMIT() asm volatile("cp.async.commit_group;" ::: "memory")
#define CP_WAIT0()  asm volatile("cp.async.wait_group 0;" ::: "memory")
#define CP_WAIT1()  asm volatile("cp.async.wait_group 1;" ::: "memory")

// ============================================================================
// Device-global scratch (alloc-free per harness rules)
// ============================================================================
__device__ float g_S[(size_t)NB * NP * MP];              // logits f32
__device__ __nv_bfloat16 g_Fh[(size_t)NB * NP * KPD];    // F [b][n][k] hi
__device__ __nv_bfloat16 g_Fl[(size_t)NB * NP * KPD];
__device__ __nv_bfloat16 g_Gh[(size_t)NB * MP * KPD];    // G [b][m][k]
__device__ __nv_bfloat16 g_Gl[(size_t)NB * MP * KPD];
__device__ __nv_bfloat16 g_Hth[(size_t)NB * CC * MP];    // Ht [b][c][m]
__device__ __nv_bfloat16 g_Htl[(size_t)NB * CC * MP];
__device__ __nv_bfloat16 g_Qh [(size_t)NB * CC * MP];    // Ht^2 [b][c][m]
__device__ __nv_bfloat16 g_Ql [(size_t)NB * CC * MP];
__device__ __nv_bfloat16 g_Sh[(size_t)NB * NP * MP];     // softmax probs
__device__ __nv_bfloat16 g_Sl[(size_t)NB * NP * MP];
// Conv staging (reused sequentially for c_1x, s_1x, s_x)
__device__ __nv_bfloat16 g_Xth[(size_t)NB * NP * KPD];   // X^T [b][i][k] hi
__device__ __nv_bfloat16 g_Xtl[(size_t)NB * NP * KPD];
__device__ __nv_bfloat16 g_Wh[(size_t)KPD * KPD];        // W [j][k] hi
__device__ __nv_bfloat16 g_Wl[(size_t)KPD * KPD];

// ============================================================================
// Split / transpose kernels
// ============================================================================
__global__ void __launch_bounds__(256)
split_xt(const float* __restrict__ X)
{
    __shared__ float tile[32][33];
    int b = blockIdx.z;
    int i0 = blockIdx.x * 32, k0 = blockIdx.y * 32;
    int tx = threadIdx.x & 31, ty = threadIdx.x >> 5;   // ty 0..7
    const float* Xb = X + (size_t)b * KPD * NP;
#pragma unroll
    for (int r = 0; r < 4; r++) {
        int k = ty + r * 8;
        tile[k][tx] = Xb[(size_t)(k0 + k) * NP + i0 + tx];
    }
    __syncthreads();
    size_t ob = (size_t)b * NP * KPD;
#pragma unroll
    for (int r = 0; r < 4; r++) {
        int i = ty + r * 8;
        float v = tile[tx][i];
        __nv_bfloat16 h = __float2bfloat16(v);
        __nv_bfloat16 l = __float2bfloat16(v - __bfloat162float(h));
        size_t idx = ob + (size_t)(i0 + i) * KPD + k0 + tx;
        g_Xth[idx] = h;
        g_Xtl[idx] = l;
    }
}

__global__ void __launch_bounds__(256)
split_wk(const float* __restrict__ W)
{
    int idx = blockIdx.x * 256 + threadIdx.x;   // each handles 2 floats
    float2 v = reinterpret_cast<const float2*>(W)[idx];
    uint32_t lo;
    uint32_t hi = bpack2(v.x, v.y, lo);
    reinterpret_cast<uint32_t*>(g_Wh)[idx] = hi;
    reinterpret_cast<uint32_t*>(g_Wl)[idx] = lo;
}

// ============================================================================
// Pipeline geometry (KC = 32, 80B row stride — proven conflict-free config)
// ============================================================================
#define P_ARR  10240
#define P_STG  (4 * P_ARR)
#define P_SMEM (2 * P_STG)      // 81920 -> 2 CTAs/SM (128-thread CTAs)

// meanstd (R14 exact): 6 arrays x 10240B per stage, 1 CTA/SM
#define M_ARR  10240
#define M_STG  (6 * M_ARR)
#define M_SMEM (2 * M_STG)

// ============================================================================
// Wide-tile mainloop: 4 warps per CTA, each warp computes 64n x 64m.
// Per k16 chunk per warp: 16 LDSM.x4, 96 MMAs -> 6 MMA/LDSM (vs 4 before).
// d[nt 0..3][m8 0..7][4 regs]. Warp grid 2x2 over the 128x128 block tile.
// ============================================================================
__device__ __forceinline__ void hmma_tile64(uint32_t base, int lane,
                                            int wn, int wm, float d[4][8][4])
{
    int r8 = lane & 7;
#pragma unroll
    for (int ks = 0; ks < 2; ks++) {
        uint32_t Ah[4][4], Al[4][4];
        int arow = r8 + ((lane >> 3) & 1) * 8;
        int akb  = ks * 16 + ((lane >> 4) & 1) * 8;
#pragma unroll
        for (int nt = 0; nt < 4; nt++) {
            uint32_t aoff = (uint32_t)((wn * 64 + nt * 16 + arow) * 80 + akb * 2);
            LDM_X4(Ah[nt][0], Ah[nt][1], Ah[nt][2], Ah[nt][3], base + 0 * P_ARR + aoff);
            LDM_X4(Al[nt][0], Al[nt][1], Al[nt][2], Al[nt][3], base + 1 * P_ARR + aoff);
        }
        int brow = r8 + ((lane >> 4) & 1) * 8;
        int bkb  = ks * 16 + ((lane >> 3) & 1) * 8;
#pragma unroll
        for (int mg = 0; mg < 4; mg++) {
            uint32_t boff = (uint32_t)((wm * 64 + mg * 16 + brow) * 80 + bkb * 2);
            uint32_t Bh[4], Bl[4];
            LDM_X4(Bh[0], Bh[1], Bh[2], Bh[3], base + 2 * P_ARR + boff);
            LDM_X4(Bl[0], Bl[1], Bl[2], Bl[3], base + 3 * P_ARR + boff);
#pragma unroll
            for (int nt = 0; nt < 4; nt++) {
                float* p0 = d[nt][2 * mg];
                float* p1 = d[nt][2 * mg + 1];
                mma16816(p0, Ah[nt], Bh[0], Bh[1]);
                mma16816(p1, Ah[nt], Bh[2], Bh[3]);
                mma16816(p0, Ah[nt], Bl[0], Bl[1]);
                mma16816(p1, Ah[nt], Bl[2], Bl[3]);
                mma16816(p0, Al[nt], Bh[0], Bh[1]);
                mma16816(p1, Al[nt], Bh[2], Bh[3]);
            }
        }
    }
}

// ============================================================================
// Conv GEMM via HMMA, 128 threads. stages = KPD/32 = 16.
// ============================================================================
#define C_STAGES (KPD / 32)

__device__ __forceinline__ void conv_issue(int s, uint32_t sb, int tid,
                                           size_t xb, int a0, int b0, int swap)
{
    uint32_t base = sb + (uint32_t)(s & 1) * P_STG;
    int k0 = s * 32;
#pragma unroll
    for (int q = 0; q < 16; q++) {
        int id = q * 128 + tid;
        int arr = id >> 9, rem = id & 511, row = rem >> 2, c = rem & 3;
        const __nv_bfloat16* src;
        if (!swap) {
            if (arr == 0)      src = g_Xth + xb + (size_t)(a0 + row) * KPD + k0 + c * 8;
            else if (arr == 1) src = g_Xtl + xb + (size_t)(a0 + row) * KPD + k0 + c * 8;
            else if (arr == 2) src = g_Wh + (size_t)(b0 + row) * KPD + k0 + c * 8;
            else               src = g_Wl + (size_t)(b0 + row) * KPD + k0 + c * 8;
        } else {
            if (arr == 0)      src = g_Wh + (size_t)(a0 + row) * KPD + k0 + c * 8;
            else if (arr == 1) src = g_Wl + (size_t)(a0 + row) * KPD + k0 + c * 8;
            else if (arr == 2) src = g_Xth + xb + (size_t)(b0 + row) * KPD + k0 + c * 8;
            else               src = g_Xtl + xb + (size_t)(b0 + row) * KPD + k0 + c * 8;
        }
        uint32_t dst = base + (uint32_t)arr * P_ARR + row * 80 + c * 16;
        CP_ASYNC16(dst, (const void*)src);
    }
    CP_COMMIT();
}

// dest 0 -> F, 1 -> G: output [n][k] split, bias over columns
__global__ void __launch_bounds__(128)
conv_nk(const float* __restrict__ bias, int dest)
{
    extern __shared__ char sm[];
    uint32_t sb = smem_u32(sm);
    int tid = threadIdx.x, lane = tid & 31, warp = tid >> 5;
    int wn = warp >> 1, wm = warp & 1;
    int b = blockIdx.z, i0 = blockIdx.x * 128, j0 = blockIdx.y * 128;
    size_t xb = (size_t)b * NP * KPD;

    float d[4][8][4];
#pragma unroll
    for (int a = 0; a < 4; a++)
#pragma unroll
        for (int j = 0; j < 8; j++)
#pragma unroll
            for (int r = 0; r < 4; r++) d[a][j][r] = 0.f;

    conv_issue(0, sb, tid, xb, i0, j0, 0);
    for (int s = 0; s < C_STAGES; s++) {
        if (s + 1 < C_STAGES) { conv_issue(s + 1, sb, tid, xb, i0, j0, 0); CP_WAIT1(); }
        else                  { CP_WAIT0(); }
        __syncthreads();
        hmma_tile64(sb + (uint32_t)(s & 1) * P_STG, lane, wn, wm, d);
        __syncthreads();
    }

    size_t bb = (size_t)b * NP * KPD;
    __nv_bfloat16* Dh = (dest == 0 ? g_Fh : g_Gh) + bb;
    __nv_bfloat16* Dl = (dest == 0 ? g_Fl : g_Gl) + bb;
#pragma unroll
    for (int nt = 0; nt < 4; nt++)
#pragma unroll
        for (int m8 = 0; m8 < 8; m8++) {
            int n = i0 + wn * 64 + nt * 16 + (lane >> 2);
            int j = j0 + wm * 64 + m8 * 8 + (lane & 3) * 2;
            float2 bv = *reinterpret_cast<const float2*>(&bias[j]);
            uint32_t lo, hi;
            hi = bpack2(d[nt][m8][0] + bv.x, d[nt][m8][1] + bv.y, lo);
            *reinterpret_cast<uint32_t*>(Dh + (size_t)n * KPD + j) = hi;
            *reinterpret_cast<uint32_t*>(Dl + (size_t)n * KPD + j) = lo;
            hi = bpack2(d[nt][m8][2] + bv.x, d[nt][m8][3] + bv.y, lo);
            *reinterpret_cast<uint32_t*>(Dh + (size_t)(n + 8) * KPD + j) = hi;
            *reinterpret_cast<uint32_t*>(Dl + (size_t)(n + 8) * KPD + j) = lo;
        }
}

// Ht conv: output rows = channels -> Ht [c][m] and Ht^2 [c][m] splits
__global__ void __launch_bounds__(128)
conv_cm(const float* __restrict__ bias)
{
    extern __shared__ char sm[];
    uint32_t sb = smem_u32(sm);
    int tid = threadIdx.x, lane = tid & 31, warp = tid >> 5;
    int wc = warp >> 1, wm = warp & 1;
    int b = blockIdx.z, m0 = blockIdx.x * 128, c0 = blockIdx.y * 128;
    size_t xb = (size_t)b * NP * KPD;

    float d[4][8][4];
#pragma unroll
    for (int a = 0; a < 4; a++)
#pragma unroll
        for (int j = 0; j < 8; j++)
#pragma unroll
            for (int r = 0; r < 4; r++) d[a][j][r] = 0.f;

    conv_issue(0, sb, tid, xb, c0, m0, 1);
    for (int s = 0; s < C_STAGES; s++) {
        if (s + 1 < C_STAGES) { conv_issue(s + 1, sb, tid, xb, c0, m0, 1); CP_WAIT1(); }
        else                  { CP_WAIT0(); }
        __syncthreads();
        hmma_tile64(sb + (uint32_t)(s & 1) * P_STG, lane, wc, wm, d);
        __syncthreads();
    }

    size_t bb = (size_t)b * CC * MP;
#pragma unroll
    for (int ct = 0; ct < 4; ct++)
#pragma unroll
        for (int m8 = 0; m8 < 8; m8++) {
            int c = c0 + wc * 64 + ct * 16 + (lane >> 2);
            int m = m0 + wm * 64 + m8 * 8 + (lane & 3) * 2;
            float b0v = bias[c], b1v = bias[c + 8];
            float v0 = d[ct][m8][0] + b0v, v1 = d[ct][m8][1] + b0v;
            float v2 = d[ct][m8][2] + b1v, v3 = d[ct][m8][3] + b1v;
            size_t idx0 = bb + (size_t)c * MP + m;
            size_t idx1 = bb + (size_t)(c + 8) * MP + m;
            uint32_t lo, hi;
            hi = bpack2(v0, v1, lo);
            *reinterpret_cast<uint32_t*>(g_Hth + idx0) = hi;
            *reinterpret_cast<uint32_t*>(g_Htl + idx0) = lo;
            hi = bpack2(v0 * v0, v1 * v1, lo);
            *reinterpret_cast<uint32_t*>(g_Qh + idx0) = hi;
            *reinterpret_cast<uint32_t*>(g_Ql + idx0) = lo;
            hi = bpack2(v2, v3, lo);
            *reinterpret_cast<uint32_t*>(g_Hth + idx1) = hi;
            *reinterpret_cast<uint32_t*>(g_Htl + idx1) = lo;
            hi = bpack2(v2 * v2, v3 * v3, lo);
            *reinterpret_cast<uint32_t*>(g_Qh + idx1) = hi;
            *reinterpret_cast<uint32_t*>(g_Ql + idx1) = lo;
        }
}

// ============================================================================
// Logits GEMM via HMMA, 128 threads. stages = KPD/32 = 16.
// ============================================================================
#define L_STAGES (KPD / 32)

__device__ __forceinline__ void logits_issue(int s, uint32_t sb, int tid,
                                             int b, int n0, int m0)
{
    uint32_t base = sb + (uint32_t)(s & 1) * P_STG;
    int k0 = s * 32;
    size_t fb = (size_t)b * NP * KPD;
    size_t gb = (size_t)b * MP * KPD;
#pragma unroll
    for (int q = 0; q < 16; q++) {
        int id = q * 128 + tid;
        int arr = id >> 9, rem = id & 511, row = rem >> 2, c = rem & 3;
        const __nv_bfloat16* src;
        if (arr == 0)      src = g_Fh + fb + (size_t)(n0 + row) * KPD + k0 + c * 8;
        else if (arr == 1) src = g_Fl + fb + (size_t)(n0 + row) * KPD + k0 + c * 8;
        else if (arr == 2) src = g_Gh + gb + (size_t)(m0 + row) * KPD + k0 + c * 8;
        else               src = g_Gl + gb + (size_t)(m0 + row) * KPD + k0 + c * 8;
        uint32_t dst = base + (uint32_t)arr * P_ARR + row * 80 + c * 16;
        CP_ASYNC16(dst, (const void*)src);
    }
    CP_COMMIT();
}

__global__ void __launch_bounds__(128)
logits_hmma()
{
    extern __shared__ char sm[];
    uint32_t sb = smem_u32(sm);
    int tid = threadIdx.x, lane = tid & 31, warp = tid >> 5;
    int wn = warp >> 1, wm = warp & 1;
    int b = blockIdx.z, m0 = blockIdx.x * 128, n0 = blockIdx.y * 128;
    float* Sb = g_S + (size_t)b * NP * MP;

    float d[4][8][4];
#pragma unroll
    for (int a = 0; a < 4; a++)
#pragma unroll
        for (int j = 0; j < 8; j++)
#pragma unroll
            for (int r = 0; r < 4; r++) d[a][j][r] = 0.f;

    logits_issue(0, sb, tid, b, n0, m0);
    for (int s = 0; s < L_STAGES; s++) {
        if (s + 1 < L_STAGES) { logits_issue(s + 1, sb, tid, b, n0, m0); CP_WAIT1(); }
        else                  { CP_WAIT0(); }
        __syncthreads();
        hmma_tile64(sb + (uint32_t)(s & 1) * P_STG, lane, wn, wm, d);
        __syncthreads();
    }

#pragma unroll
    for (int nt = 0; nt < 4; nt++)
#pragma unroll
        for (int m8 = 0; m8 < 8; m8++) {
            int n = n0 + wn * 64 + nt * 16 + (lane >> 2);
            int m = m0 + wm * 64 + m8 * 8 + (lane & 3) * 2;
            *reinterpret_cast<float2*>(&Sb[(size_t)n * MP + m]) =
                make_float2(d[nt][m8][0], d[nt][m8][1]);
            *reinterpret_cast<float2*>(&Sb[(size_t)(n + 8) * MP + m]) =
                make_float2(d[nt][m8][2], d[nt][m8][3]);
        }
}

// ============================================================================
// Row softmax: f32 logits -> bf16 hi/lo probabilities.
// ============================================================================
__global__ void __launch_bounds__(256)
softmax_rows()
{
    __shared__ float red[256];
    int row = blockIdx.x;
    size_t base = (size_t)row * MP;
    int tid = threadIdx.x;

    float2 v[8];
    float lmax = -1e30f;
#pragma unroll
    for (int t = 0; t < 8; t++) {
        v[t] = *reinterpret_cast<const float2*>(&g_S[base + tid * 2 + t * 512]);
        lmax = fmaxf(lmax, fmaxf(v[t].x, v[t].y));
    }
    red[tid] = lmax;
    __syncthreads();
    for (int s = 128; s > 0; s >>= 1) {
        if (tid < s) red[tid] = fmaxf(red[tid], red[tid + s]);
        __syncthreads();
    }
    float m = red[0];
    __syncthreads();

    float lsum = 0.f;
#pragma unroll
    for (int t = 0; t < 8; t++) {
        v[t].x = __expf(v[t].x - m);
        v[t].y = __expf(v[t].y - m);
        lsum += v[t].x + v[t].y;
    }
    red[tid] = lsum;
    __syncthreads();
    for (int s = 128; s > 0; s >>= 1) {
        if (tid < s) red[tid] += red[tid + s];
        __syncthreads();
    }
    float inv = 1.f / red[0];

#pragma unroll
    for (int t = 0; t < 8; t++) {
        size_t idx = base + tid * 2 + t * 512;
        uint32_t lo;
        uint32_t hi = bpack2(v[t].x * inv, v[t].y * inv, lo);
        *reinterpret_cast<uint32_t*>(&g_Sh[idx]) = hi;
        *reinterpret_cast<uint32_t*>(&g_Sl[idx]) = lo;
    }
}

// ============================================================================
// Dual GEMM (mean & e2) + fused epilogue — R14 proven config, 256 threads.
// stages = MP/32 = 128; 6 arrays x stride 80.
// ============================================================================
#define M_STAGES (MP / 32)

__device__ __forceinline__ void meanstd_issue(int s, uint32_t sb, int tid,
                                              int b, int cc0, int n0)
{
    uint32_t base = sb + (uint32_t)(s & 1) * M_STG;
    int mm = s * 32;
    size_t hb = (size_t)b * CC * MP;
    size_t pb = (size_t)b * NP * MP;
#pragma unroll
    for (int q = 0; q < 12; q++) {
        int id = q * 256 + tid;
        int arr = id >> 9, rem = id & 511, row = rem >> 2, c = rem & 3;
        const __nv_bfloat16* src;
        if (arr == 0)      src = g_Hth + hb + (size_t)(cc0 + row) * MP + mm + c * 8;
        else if (arr == 1) src = g_Htl + hb + (size_t)(cc0 + row) * MP + mm + c * 8;
        else if (arr == 2) src = g_Qh  + hb + (size_t)(cc0 + row) * MP + mm + c * 8;
        else if (arr == 3) src = g_Ql  + hb + (size_t)(cc0 + row) * MP + mm + c * 8;
        else if (arr == 4) src = g_Sh  + pb + (size_t)(n0 + row) * MP + mm + c * 8;
        else               src = g_Sl  + pb + (size_t)(n0 + row) * MP + mm + c * 8;
        uint32_t dst = base + (uint32_t)arr * M_ARR + row * 80 + c * 16;
        CP_ASYNC16(dst, (const void*)src);
    }
    CP_COMMIT();
}

__global__ void __launch_bounds__(256, 1)
meanstd_hmma(const float* __restrict__ c_x, float* __restrict__ out)
{
    extern __shared__ char sm[];
    uint32_t sb = smem_u32(sm);
    int tid = threadIdx.x, lane = tid & 31, warp = tid >> 5;
    int wc = warp >> 1, wn = warp & 1;
    int b = blockIdx.z, n0 = blockIdx.x * 128, cc0 = blockIdx.y * 128;

    float dm[2][8][4], de[2][8][4];
#pragma unroll
    for (int a = 0; a < 2; a++)
#pragma unroll
        for (int j = 0; j < 8; j++)
#pragma unroll
            for (int r = 0; r < 4; r++) { dm[a][j][r] = 0.f; de[a][j][r] = 0.f; }

    meanstd_issue(0, sb, tid, b, cc0, n0);

    int r8 = lane & 7;
    for (int s = 0; s < M_STAGES; s++) {
        if (s + 1 < M_STAGES) { meanstd_issue(s + 1, sb, tid, b, cc0, n0); CP_WAIT1(); }
        else                  { CP_WAIT0(); }
        __syncthreads();

        uint32_t base = sb + (uint32_t)(s & 1) * M_STG;
#pragma unroll
        for (int ks = 0; ks < 2; ks++) {
            uint32_t Hh[2][4], Hl[2][4], Wh[2][4], Wl[2][4];
            int arow = r8 + ((lane >> 3) & 1) * 8;
            int akb  = ks * 16 + ((lane >> 4) & 1) * 8;
#pragma unroll
            for (int ct = 0; ct < 2; ct++) {
                uint32_t aoff = (uint32_t)((wc * 32 + ct * 16 + arow) * 80 + akb * 2);
                LDM_X4(Hh[ct][0], Hh[ct][1], Hh[ct][2], Hh[ct][3], base + 0 * M_ARR + aoff);
                LDM_X4(Hl[ct][0], Hl[ct][1], Hl[ct][2], Hl[ct][3], base + 1 * M_ARR + aoff);
                LDM_X4(Wh[ct][0], Wh[ct][1], Wh[ct][2], Wh[ct][3], base + 2 * M_ARR + aoff);
                LDM_X4(Wl[ct][0], Wl[ct][1], Wl[ct][2], Wl[ct][3], base + 3 * M_ARR + aoff);
            }
            int brow = r8 + ((lane >> 4) & 1) * 8;
            int bkb  = ks * 16 + ((lane >> 3) & 1) * 8;
#pragma unroll
            for (int ng = 0; ng < 4; ng++) {
                uint32_t boff = (uint32_t)((wn * 64 + ng * 16 + brow) * 80 + bkb * 2);
                uint32_t Sh4[4], Sl4[4];
                LDM_X4(Sh4[0], Sh4[1], Sh4[2], Sh4[3], base + 4 * M_ARR + boff);
                LDM_X4(Sl4[0], Sl4[1], Sl4[2], Sl4[3], base + 5 * M_ARR + boff);
#pragma unroll
                for (int ct = 0; ct < 2; ct++) {
#pragma unroll
                    for (int sub = 0; sub < 2; sub++) {
                        uint32_t s0 = Sh4[2 * sub], s1 = Sh4[2 * sub + 1];
                        uint32_t t0 = Sl4[2 * sub], t1 = Sl4[2 * sub + 1];
                        float* pm = dm[ct][2 * ng + sub];
                        float* pe = de[ct][2 * ng + sub];
                        mma16816(pm, Hh[ct], s0, s1);
                        mma16816(pe, Wh[ct], s0, s1);
                        mma16816(pm, Hh[ct], t0, t1);
                        mma16816(pe, Wh[ct], t0, t1);
                        mma16816(pm, Hl[ct], s0, s1);
                        mma16816(pe, Wl[ct], s0, s1);
                    }
                }
            }
        }
        __syncthreads();
    }

    // Fused epilogue: out[b][c][n] = sqrt(relu(e2 - mean^2)) * c_x + mean
#pragma unroll
    for (int ct = 0; ct < 2; ct++)
#pragma unroll
        for (int j = 0; j < 8; j++) {
            int cbase = cc0 + wc * 32 + ct * 16 + (lane >> 2);
            int n = n0 + wn * 64 + j * 8 + (lane & 3) * 2;
#pragma unroll
            for (int rr = 0; rr < 2; rr++) {
                int cr = cbase + rr * 8;
                float m0v = dm[ct][j][2 * rr],     e0 = de[ct][j][2 * rr];
                float m1v = dm[ct][j][2 * rr + 1], e1 = de[ct][j][2 * rr + 1];
                size_t idx = ((size_t)b * CC + cr) * NP + n;
                float2 cx = *reinterpret_cast<const float2*>(&c_x[idx]);
                float sd0 = sqrtf(fmaxf(e0 - m0v * m0v, 0.f));
                float sd1 = sqrtf(fmaxf(e1 - m1v * m1v, 0.f));
                *reinterpret_cast<float2*>(&out[idx]) =
                    make_float2(sd0 * cx.x + m0v, sd1 * cx.y + m1v);
            }
        }
}

// ============================================================================
// Launch
// ============================================================================
extern "C" void kernel_launch(void* const* d_in, const int* in_sizes, int n_in,
                              void* d_out, int out_size)
{
    const float* c_x  = (const float*)d_in[0];
    const float* s_x  = (const float*)d_in[1];
    const float* c_1x = (const float*)d_in[2];
    const float* s_1x = (const float*)d_in[3];
    const float* f_w  = (const float*)d_in[4];
    const float* f_b  = (const float*)d_in[5];
    const float* g_w  = (const float*)d_in[6];
    const float* g_b  = (const float*)d_in[7];
    const float* h_w  = (const float*)d_in[8];
    const float* h_b  = (const float*)d_in[9];
    float* out = (float*)d_out;

    (void)in_sizes; (void)n_in; (void)out_size;

    static int attr_done = 0;
    if (!attr_done) {
        cudaFuncSetAttribute(conv_nk,
                             cudaFuncAttributeMaxDynamicSharedMemorySize, P_SMEM);
        cudaFuncSetAttribute(conv_cm,
                             cudaFuncAttributeMaxDynamicSharedMemorySize, P_SMEM);
        cudaFuncSetAttribute(logits_hmma,
                             cudaFuncAttributeMaxDynamicSharedMemorySize, P_SMEM);
        cudaFuncSetAttribute(meanstd_hmma,
                             cudaFuncAttributeMaxDynamicSharedMemorySize, M_SMEM);
        attr_done = 1;
    }

    dim3 gridT(NP / 32, KPD / 32, NB);     // split_xt: (128, 16, 4)
    dim3 gridC(NP / 128, KPD / 128, NB);   // convs: (32, 4, 4)

    // F = f(c_1x)
    split_wk<<<512, 256>>>(f_w);
    split_xt<<<gridT, 256>>>(c_1x);
    conv_nk<<<gridC, 128, P_SMEM>>>(f_b, 0);

    // G = g(s_1x)
    split_wk<<<512, 256>>>(g_w);
    split_xt<<<gridT, 256>>>(s_1x);
    conv_nk<<<gridC, 128, P_SMEM>>>(g_b, 1);

    // Ht (+ Ht^2) = h(s_x), transposed output
    split_wk<<<512, 256>>>(h_w);
    split_xt<<<gridT, 256>>>(s_x);
    conv_cm<<<gridC, 128, P_SMEM>>>(h_b);

    dim3 gridL(MP / 128, NP / 128, NB);    // (32, 32, 4)
    logits_hmma<<<gridL, 128, P_SMEM>>>();

    softmax_rows<<<NB * NP, 256>>>();      // 16384 rows

    dim3 gridM(NP / 128, CC / 128, NB);    // (32, 4, 4)
    meanstd_hmma<<<gridM, 256, M_SMEM>>>(c_x, out);
}